// round 1
// baseline (speedup 1.0000x reference)
#include <cuda_runtime.h>

#define Hh 512
#define Ww 512
#define TH 56
#define TW 128
#define ROWSH 66   /* TH + 10, multiple of 11 */
#define COLSH 138  /* TW + 10 */

typedef unsigned long long pk_t;

__device__ __forceinline__ pk_t pk2(float a, float b) {
    pk_t r; asm("mov.b64 %0, {%1, %2};" : "=l"(r) : "f"(a), "f"(b)); return r;
}
__device__ __forceinline__ pk_t padd(pk_t a, pk_t b) {
    pk_t r; asm("add.rn.f32x2 %0, %1, %2;" : "=l"(r) : "l"(a), "l"(b)); return r;
}
__device__ __forceinline__ pk_t pmul(pk_t a, pk_t b) {
    pk_t r; asm("mul.rn.f32x2 %0, %1, %2;" : "=l"(r) : "l"(a), "l"(b)); return r;
}
__device__ __forceinline__ pk_t pfma(pk_t a, pk_t b, pk_t c) {
    pk_t r; asm("fma.rn.f32x2 %0, %1, %2, %3;" : "=l"(r) : "l"(a), "l"(b), "l"(c)); return r;
}

// out[b,i,j] = sum_{1<=|a|+|b|<=5} w_{|a|+|b|} * s[b, (i+a)%H, (j+b)%W]
// Row-decomposed: F_m(row)[j] = sum_{t=0..5-m} W(m+t) * R_t[j],  W(0)=0
//   R_0 = x[j], R_t = x[j-t] + x[j+t]
// out[i] = F_0(i) + sum_{m=1..5} ( F_m(i-m) + F_m(i+m) )
// Streaming rows top->bottom with 11 cyclic f32x2 accumulators (2 batches packed).
__global__ __launch_bounds__(TW, 3)
void lc_kernel(const float* __restrict__ in, const float* __restrict__ w,
               float* __restrict__ out)
{
    extern __shared__ pk_t sh[];   // ROWSH * COLSH packed {batchA, batchB}

    const int tid = threadIdx.x;
    const int j0  = blockIdx.x * TW;
    const int i0  = blockIdx.y * TH;
    const int bp  = blockIdx.z;

    const float* gA = in  + (size_t)(2 * bp) * (Hh * Ww);
    const float* gB = gA + Hh * Ww;
    float*       oA = out + (size_t)(2 * bp) * (Hh * Ww);
    float*       oB = oA + Hh * Ww;

    // ---- load tile (rows i0-5..i0+60 wrapped, cols j0-5..j0+132 wrapped) ----
    for (int idx = tid; idx < ROWSH * COLSH; idx += TW) {
        int row = idx / COLSH;
        int col = idx - row * COLSH;
        int gr  = (i0 - 5 + row) & (Hh - 1);
        int gc  = (j0 - 5 + col) & (Ww - 1);
        float a = __ldg(&gA[gr * Ww + gc]);
        float b = __ldg(&gB[gr * Ww + gc]);
        sh[idx] = pk2(a, b);
    }

    const pk_t w1 = pk2(__ldg(&w[0]), __ldg(&w[0]));
    const pk_t w2 = pk2(__ldg(&w[1]), __ldg(&w[1]));
    const pk_t w3 = pk2(__ldg(&w[2]), __ldg(&w[2]));
    const pk_t w4 = pk2(__ldg(&w[3]), __ldg(&w[3]));
    const pk_t w5 = pk2(__ldg(&w[4]), __ldg(&w[4]));
    const pk_t zz = pk2(0.0f, 0.0f);

    __syncthreads();

    pk_t acc[11];
#pragma unroll
    for (int s = 0; s < 11; s++) acc[s] = zz;

    for (int ko = 0; ko < ROWSH; ko += 11) {
#pragma unroll
        for (int u = 0; u < 11; u++) {
            const int k = ko + u;                 // tile row; k mod 11 == u
            const pk_t* rp = sh + k * COLSH + tid;
            pk_t v0 = rp[0],  v1 = rp[1], v2 = rp[2], v3 = rp[3], v4 = rp[4];
            pk_t v5 = rp[5],  v6 = rp[6], v7 = rp[7], v8 = rp[8], v9 = rp[9];
            pk_t v10 = rp[10];

            pk_t R0 = v5;
            pk_t R1 = padd(v4, v6);
            pk_t R2 = padd(v3, v7);
            pk_t R3 = padd(v2, v8);
            pk_t R4 = padd(v1, v9);
            pk_t R5 = padd(v0, v10);

            pk_t F0 = pfma(w5, R5, pfma(w4, R4, pfma(w3, R3, pfma(w2, R2, pmul(w1, R1)))));
            pk_t F1 = pfma(w5, R4, pfma(w4, R3, pfma(w3, R2, pfma(w2, R1, pmul(w1, R0)))));
            pk_t F2 = pfma(w5, R3, pfma(w4, R2, pfma(w3, R1, pmul(w2, R0))));
            pk_t F3 = pfma(w5, R2, pfma(w4, R1, pmul(w3, R0)));
            pk_t F4 = pfma(w5, R1, pmul(w4, R0));
            pk_t F5 = pmul(w5, R0);

            // row r = i0-5+k contributes F_m to outputs r-m and r+m.
            // slot(output) emitted at iter k_e, slot = k_e % 11; k_e = k+5±m here.
            acc[(u + 5)  % 11] = padd(acc[(u + 5)  % 11], F0);
            acc[(u + 6)  % 11] = padd(acc[(u + 6)  % 11], F1);
            acc[(u + 4)  % 11] = padd(acc[(u + 4)  % 11], F1);
            acc[(u + 7)  % 11] = padd(acc[(u + 7)  % 11], F2);
            acc[(u + 3)  % 11] = padd(acc[(u + 3)  % 11], F2);
            acc[(u + 8)  % 11] = padd(acc[(u + 8)  % 11], F3);
            acc[(u + 2)  % 11] = padd(acc[(u + 2)  % 11], F3);
            acc[(u + 9)  % 11] = padd(acc[(u + 9)  % 11], F4);
            acc[(u + 1)  % 11] = padd(acc[(u + 1)  % 11], F4);
            acc[(u + 10) % 11] = padd(acc[(u + 10) % 11], F5);
            acc[u]             = padd(acc[u],             F5);

            if (k >= 10) {
                int o = i0 + k - 10;              // output row (slot u complete)
                if (o < Hh) {
                    int oi = o * Ww + j0 + tid;
                    pk_t a = acc[u];
                    oA[oi] = __uint_as_float((unsigned)a);
                    oB[oi] = __uint_as_float((unsigned)(a >> 32));
                }
            }
            acc[u] = zz;  // recycle slot for output emitted at k+11
        }
    }
}

extern "C" void kernel_launch(void* const* d_in, const int* in_sizes, int n_in,
                              void* d_out, int out_size)
{
    // identify inputs by size (grid_spikes = B*H*W, weights = 5)
    int gi = 0, wi = 1;
    if (in_sizes[0] == 5) { gi = 1; wi = 0; }
    const float* in = (const float*)d_in[gi];
    const float* w  = (const float*)d_in[wi];
    float* out = (float*)d_out;

    int B = in_sizes[gi] / (Hh * Ww);     // 64
    size_t smem = (size_t)ROWSH * COLSH * sizeof(pk_t);  // 72864 B

    cudaFuncSetAttribute(lc_kernel, cudaFuncAttributeMaxDynamicSharedMemorySize, (int)smem);

    dim3 grid(Ww / TW, (Hh + TH - 1) / TH, B / 2);  // 4 x 10 x 32
    lc_kernel<<<grid, TW, smem>>>(in, w, out);
}

// round 2
// speedup vs baseline: 1.2131x; 1.2131x over previous
#include <cuda_runtime.h>

#define Hh 512
#define Ww 512
#define TH 56          /* output rows per block; ROWSH = TH+10 = 66 = 6*11  */
#define NT 128         /* threads per block; each handles 2 output columns  */
#define TWC 256        /* output cols per block = 2*NT                      */
#define COLS 266       /* TWC + 10 halo cols                                */
#define CSTR 268       /* shared row stride (pk), even for 16B alignment    */
#define NCH 6          /* chunks of 11 rows: 66 total                       */
#define BUFP (11 * CSTR)

typedef unsigned long long pk_t;

__device__ __forceinline__ pk_t pk2(float a, float b) {
    pk_t r; asm("mov.b64 %0, {%1, %2};" : "=l"(r) : "f"(a), "f"(b)); return r;
}
__device__ __forceinline__ pk_t padd(pk_t a, pk_t b) {
    pk_t r; asm("add.rn.f32x2 %0, %1, %2;" : "=l"(r) : "l"(a), "l"(b)); return r;
}
__device__ __forceinline__ pk_t pmul(pk_t a, pk_t b) {
    pk_t r; asm("mul.rn.f32x2 %0, %1, %2;" : "=l"(r) : "l"(a), "l"(b)); return r;
}
__device__ __forceinline__ pk_t pfma(pk_t a, pk_t b, pk_t c) {
    pk_t r; asm("fma.rn.f32x2 %0, %1, %2, %3;" : "=l"(r) : "l"(a), "l"(b), "l"(c)); return r;
}
__device__ __forceinline__ float plo(pk_t a) { return __uint_as_float((unsigned)a); }
__device__ __forceinline__ float phi(pk_t a) { return __uint_as_float((unsigned)(a >> 32)); }

// Load one 11-row chunk (rows base_r..base_r+10 wrapped, cols j0-5..j0+260 wrapped)
// into buf as packed {batchA, batchB}.
__device__ __forceinline__ void load_chunk(pk_t* __restrict__ buf,
                                           const float* __restrict__ gA,
                                           const float* __restrict__ gB,
                                           int base_r, int j0, int tid)
{
#pragma unroll
    for (int r = 0; r < 11; r++) {
        const int gr = (base_r + r) & (Hh - 1);
        const float* rowA = gA + gr * Ww;
        const float* rowB = gB + gr * Ww;
#pragma unroll
        for (int s = 0; s < 3; s++) {
            const int col = tid + s * NT;
            if (s < 2 || col < COLS) {
                const int gc = (j0 - 5 + col) & (Ww - 1);
                buf[r * CSTR + col] = pk2(__ldg(&rowA[gc]), __ldg(&rowB[gc]));
            }
        }
    }
}

// out[b,i,j] = sum_{1<=|a|+|c|<=5} w_{|a|+|c|} * s[b,(i+a)%H,(j+c)%W]   (torus)
// Per row: R_t[j] = x[j-t]+x[j+t]; F_m = sum_t W(m+t) R_t; row r feeds outputs r±m.
// 11 cyclic accumulators stream rows top->bottom; 2 batches packed in f32x2;
// 2 adjacent output columns per thread (shared LDS.128 window v0..v12).
__global__ __launch_bounds__(NT, 4)
void lc_kernel(const float* __restrict__ in, const float* __restrict__ w,
               float* __restrict__ out)
{
    extern __shared__ pk_t sh[];   // 2 * 11 * CSTR

    const int tid = threadIdx.x;
    const int j0  = blockIdx.x * TWC;
    const int i0  = blockIdx.y * TH;
    const int bp  = blockIdx.z;

    const float* gA = in  + (size_t)(2 * bp) * (Hh * Ww);
    const float* gB = gA + Hh * Ww;
    float*       oA = out + (size_t)(2 * bp) * (Hh * Ww);
    float*       oB = oA + Hh * Ww;

    const pk_t w1 = pk2(__ldg(&w[0]), __ldg(&w[0]));
    const pk_t w2 = pk2(__ldg(&w[1]), __ldg(&w[1]));
    const pk_t w3 = pk2(__ldg(&w[2]), __ldg(&w[2]));
    const pk_t w4 = pk2(__ldg(&w[3]), __ldg(&w[3]));
    const pk_t w5 = pk2(__ldg(&w[4]), __ldg(&w[4]));
    const pk_t zz = pk2(0.0f, 0.0f);

    pk_t accA[11], accB[11];
#pragma unroll
    for (int s = 0; s < 11; s++) { accA[s] = zz; accB[s] = zz; }

    load_chunk(sh, gA, gB, i0 - 5, j0, tid);
    __syncthreads();

    for (int c = 0; c < NCH; c++) {
        const pk_t* cur = sh + (c & 1) * BUFP;
        if (c + 1 < NCH)
            load_chunk(sh + ((c + 1) & 1) * BUFP, gA, gB, i0 - 5 + (c + 1) * 11, j0, tid);

#pragma unroll
        for (int u = 0; u < 11; u++) {
            const int k = c * 11 + u;             // tile row; k % 11 == u
            const pk_t* rp = cur + u * CSTR + 2 * tid;

            pk_t v0, v1, v2, v3, v4, v5, v6, v7, v8, v9, v10, v11, v12;
            {
                const uint4* q = (const uint4*)rp;
                uint4 a = q[0], b = q[1], cq = q[2], d = q[3], e = q[4], f = q[5];
                v0  = ((pk_t)a.y  << 32) | a.x;   v1  = ((pk_t)a.w  << 32) | a.z;
                v2  = ((pk_t)b.y  << 32) | b.x;   v3  = ((pk_t)b.w  << 32) | b.z;
                v4  = ((pk_t)cq.y << 32) | cq.x;  v5  = ((pk_t)cq.w << 32) | cq.z;
                v6  = ((pk_t)d.y  << 32) | d.x;   v7  = ((pk_t)d.w  << 32) | d.z;
                v8  = ((pk_t)e.y  << 32) | e.x;   v9  = ((pk_t)e.w  << 32) | e.z;
                v10 = ((pk_t)f.y  << 32) | f.x;   v11 = ((pk_t)f.w  << 32) | f.z;
                v12 = rp[12];
            }

            // column A (center v5)
            {
                pk_t R0 = v5;
                pk_t R1 = padd(v4, v6);
                pk_t R2 = padd(v3, v7);
                pk_t R3 = padd(v2, v8);
                pk_t R4 = padd(v1, v9);
                pk_t R5 = padd(v0, v10);
                pk_t F0 = pfma(w5, R5, pfma(w4, R4, pfma(w3, R3, pfma(w2, R2, pmul(w1, R1)))));
                pk_t F1 = pfma(w5, R4, pfma(w4, R3, pfma(w3, R2, pfma(w2, R1, pmul(w1, R0)))));
                pk_t F2 = pfma(w5, R3, pfma(w4, R2, pfma(w3, R1, pmul(w2, R0))));
                pk_t F3 = pfma(w5, R2, pfma(w4, R1, pmul(w3, R0)));
                pk_t F4 = pfma(w5, R1, pmul(w4, R0));
                pk_t F5 = pmul(w5, R0);
                accA[(u + 5)  % 11] = padd(accA[(u + 5)  % 11], F0);
                accA[(u + 6)  % 11] = padd(accA[(u + 6)  % 11], F1);
                accA[(u + 4)  % 11] = padd(accA[(u + 4)  % 11], F1);
                accA[(u + 7)  % 11] = padd(accA[(u + 7)  % 11], F2);
                accA[(u + 3)  % 11] = padd(accA[(u + 3)  % 11], F2);
                accA[(u + 8)  % 11] = padd(accA[(u + 8)  % 11], F3);
                accA[(u + 2)  % 11] = padd(accA[(u + 2)  % 11], F3);
                accA[(u + 9)  % 11] = padd(accA[(u + 9)  % 11], F4);
                accA[(u + 1)  % 11] = padd(accA[(u + 1)  % 11], F4);
                accA[(u + 10) % 11] = padd(accA[(u + 10) % 11], F5);
                accA[u]             = padd(accA[u],             F5);
            }
            // column B (center v6)
            {
                pk_t R0 = v6;
                pk_t R1 = padd(v5, v7);
                pk_t R2 = padd(v4, v8);
                pk_t R3 = padd(v3, v9);
                pk_t R4 = padd(v2, v10);
                pk_t R5 = padd(v1, v11);
                (void)v12;
                R5 = padd(v1, v11);
                pk_t F0 = pfma(w5, R5, pfma(w4, R4, pfma(w3, R3, pfma(w2, R2, pmul(w1, R1)))));
                pk_t F1 = pfma(w5, R4, pfma(w4, R3, pfma(w3, R2, pfma(w2, R1, pmul(w1, R0)))));
                pk_t F2 = pfma(w5, R3, pfma(w4, R2, pfma(w3, R1, pmul(w2, R0))));
                pk_t F3 = pfma(w5, R2, pfma(w4, R1, pmul(w3, R0)));
                pk_t F4 = pfma(w5, R1, pmul(w4, R0));
                pk_t F5 = pmul(w5, R0);
                accB[(u + 5)  % 11] = padd(accB[(u + 5)  % 11], F0);
                accB[(u + 6)  % 11] = padd(accB[(u + 6)  % 11], F1);
                accB[(u + 4)  % 11] = padd(accB[(u + 4)  % 11], F1);
                accB[(u + 7)  % 11] = padd(accB[(u + 7)  % 11], F2);
                accB[(u + 3)  % 11] = padd(accB[(u + 3)  % 11], F2);
                accB[(u + 8)  % 11] = padd(accB[(u + 8)  % 11], F3);
                accB[(u + 2)  % 11] = padd(accB[(u + 2)  % 11], F3);
                accB[(u + 9)  % 11] = padd(accB[(u + 9)  % 11], F4);
                accB[(u + 1)  % 11] = padd(accB[(u + 1)  % 11], F4);
                accB[(u + 10) % 11] = padd(accB[(u + 10) % 11], F5);
                accB[u]             = padd(accB[u],             F5);
            }

            // wait: column B's R5 must use v1..v11 window -> centers v6: v[6-5]=v1, v[6+5]=v11. OK.
            if (k >= 10) {
                const int o = i0 + k - 10;
                if (o < Hh) {
                    const int oi = o * Ww + j0 + 2 * tid;
                    float2 ra = make_float2(plo(accA[u]), plo(accB[u]));
                    float2 rb = make_float2(phi(accA[u]), phi(accB[u]));
                    *(float2*)(oA + oi) = ra;
                    *(float2*)(oB + oi) = rb;
                }
            }
            accA[u] = zz;
            accB[u] = zz;
        }
        __syncthreads();
    }
}

extern "C" void kernel_launch(void* const* d_in, const int* in_sizes, int n_in,
                              void* d_out, int out_size)
{
    int gi = 0, wi = 1;
    if (in_sizes[0] == 5) { gi = 1; wi = 0; }
    const float* in = (const float*)d_in[gi];
    const float* w  = (const float*)d_in[wi];
    float* out = (float*)d_out;

    int B = in_sizes[gi] / (Hh * Ww);                 // 64
    size_t smem = (size_t)2 * BUFP * sizeof(pk_t);    // 2*11*268*8 = 47168 B

    static int attr_set = 0;
    if (!attr_set) {
        cudaFuncSetAttribute(lc_kernel, cudaFuncAttributeMaxDynamicSharedMemorySize, (int)smem);
        attr_set = 1;
    }

    dim3 grid(Ww / TWC, (Hh + TH - 1) / TH, B / 2);   // 2 x 10 x 32 = 640
    lc_kernel<<<grid, NT, smem>>>(in, w, out);
}